// round 2
// baseline (speedup 1.0000x reference)
#include <cuda_runtime.h>

#define NK   10     // knots per feature
#define NSEG 9      // segments
#define FF   256    // features (fixed by problem)
#define VROWS 2     // rows per thread per iteration (ILP)

// ---------------- device-global scratch (no allocations allowed) ----------------
__device__ float4 g_coef4[NSEG * FF];   // [seg][f] : (y, b*h, c*h^2, d*h^3)  (normalized-w form)
__device__ float2 g_k0inv[FF];          // (k0, 1/h_avg) for uniform fast path
__device__ float  g_knotsg[FF * NK];    // [f][k] raw knots (generic-path scan)
__device__ float2 g_kx2[FF * NSEG];     // (kx_i, 1/h_i) generic-path per-segment
__device__ int    g_uniform;            // 1 if all features have (near-)uniform knots

// ---------------- kernel 1: per-feature natural cubic spline coefficients ----------------
__global__ void coeff_kernel(const float* __restrict__ W) {
    __shared__ int s_uni;
    int f = threadIdx.x;
    if (f == 0) s_uni = 1;
    __syncthreads();

    float kx[NK], yv[NK];
#pragma unroll
    for (int j = 0; j < NK; j++) {
        kx[j] = W[f * NK + j];
        yv[j] = (j & 1) ? -1.0f : 1.0f;
        g_knotsg[f * NK + j] = kx[j];
    }
    float h[NSEG], sl[NSEG];
#pragma unroll
    for (int j = 0; j < NSEG; j++) {
        h[j]  = kx[j + 1] - kx[j];
        sl[j] = (yv[j + 1] - yv[j]) / h[j];
    }
    // Thomas algorithm: m=8 interior second derivatives.
    // diag_i = 2(h_i + h_{i+1}); A[i,i+1] = A[i+1,i] = h_{i+1}; rhs_i = 6(sl_{i+1}-sl_i)
    float cp[8], dp[8];
    {
        float dg  = 2.0f * (h[0] + h[1]);
        float inv = 1.0f / dg;
        cp[0] = h[1] * inv;
        dp[0] = 6.0f * (sl[1] - sl[0]) * inv;
#pragma unroll
        for (int i = 1; i < 8; i++) {
            float dg2 = 2.0f * (h[i] + h[i + 1]);
            float sub = h[i];
            float den = dg2 - sub * cp[i - 1];
            float inv2 = 1.0f / den;
            cp[i] = (i < 7) ? h[i + 1] * inv2 : 0.0f;
            dp[i] = (6.0f * (sl[i + 1] - sl[i]) - sub * dp[i - 1]) * inv2;
        }
    }
    float M[NK];
    M[0] = 0.0f; M[9] = 0.0f;
    M[8] = dp[7];
#pragma unroll
    for (int i = 6; i >= 0; i--)
        M[i + 1] = dp[i] - cp[i] * M[i + 2];

    // uniformity check
    float havg  = (kx[9] - kx[0]) * (1.0f / 9.0f);
    float range = fabsf(kx[9] - kx[0]) + 1e-30f;
    float dev = 0.0f;
#pragma unroll
    for (int j = 0; j < NK; j++)
        dev = fmaxf(dev, fabsf(kx[j] - (kx[0] + (float)j * havg)));
    if (!(dev <= 1e-4f * range)) atomicAnd(&s_uni, 0);

#pragma unroll
    for (int i = 0; i < NSEG; i++) {
        float c = 0.5f * M[i];
        float d = (M[i + 1] - M[i]) / (6.0f * h[i]);
        float b = sl[i] - h[i] * (2.0f * M[i] + M[i + 1]) * (1.0f / 6.0f);
        float4 cf;
        cf.x = yv[i];                      // value at left knot
        cf.y = b * h[i];                   // linear coeff in w
        cf.z = c * h[i] * h[i];            // quadratic
        cf.w = d * h[i] * h[i] * h[i];     // cubic
        g_coef4[i * FF + f] = cf;
        g_kx2[f * NSEG + i] = make_float2(kx[i], 1.0f / h[i]);
    }
    g_k0inv[f] = make_float2(kx[0], 1.0f / havg);
    __syncthreads();
    if (f == 0) g_uniform = s_uni;
}

// ---------------- spline evaluation ----------------
__device__ __forceinline__ float spline_horner(float w, float4 cf) {
    return fmaf(w, fmaf(w, fmaf(w, cf.w, cf.z), cf.y), cf.x);
}

// Fast path: uniform knots. idx = clamp(floor((x-k0)/h), 0, 8), w = t - idx.
__device__ __forceinline__ float eval_uni(float x, float nk0, float invh,
                                          const float4* __restrict__ tbl) {
    float t  = fmaf(x, invh, nk0);
    float ft = floorf(t);
    ft = fminf(fmaxf(ft, 0.0f), 8.0f);
    float w = t - ft;
    int idx = (int)ft;
    float4 cf = tbl[idx * FF];     // conflict-free: [seg][f] layout, f = lane-consecutive
    return spline_horner(w, cf);
}

// Generic path: branchless linear scan over register-resident knots (searchsorted 'right').
__device__ __forceinline__ float eval_gen(float x, const float* kn, int f,
                                          const float4* __restrict__ tbl) {
    int s = 0;
#pragma unroll
    for (int j = 1; j < NK; j++) s += (x >= kn[j]) ? 1 : 0;
    int idx = min(s, NSEG - 1);
    float2 kv = __ldg(&g_kx2[f * NSEG + idx]);
    float w = (x - kv.x) * kv.y;
    float4 cf = tbl[idx * FF];
    return spline_horner(w, cf);
}

// ---------------- RK 3/8-rule integration (9 steps, dt = 1/9) ----------------
template<bool UNI>
__device__ __forceinline__ void integrate(float st[VROWS], float nk0, float invh,
                                          const float* kn, int f,
                                          const float4* __restrict__ tbl) {
    const float dt  = 1.0f / 9.0f;
    const float dt3 = dt * (1.0f / 3.0f);
    const float dt8 = dt * 0.125f;
#pragma unroll 1
    for (int s = 0; s < 9; s++) {
#pragma unroll
        for (int v = 0; v < VROWS; v++) {
            float x0 = st[v];
            float k1 = UNI ? eval_uni(x0, nk0, invh, tbl) : eval_gen(x0, kn, f, tbl);
            float a2 = fmaf(dt3, k1, x0);
            float k2 = UNI ? eval_uni(a2, nk0, invh, tbl) : eval_gen(a2, kn, f, tbl);
            float a3 = fmaf(dt, k2, fmaf(-dt3, k1, x0));
            float k3 = UNI ? eval_uni(a3, nk0, invh, tbl) : eval_gen(a3, kn, f, tbl);
            float a4 = fmaf(dt, (k1 - k2) + k3, x0);
            float k4 = UNI ? eval_uni(a4, nk0, invh, tbl) : eval_gen(a4, kn, f, tbl);
            st[v] = fmaf(dt8, fmaf(3.0f, k2 + k3, k1 + k4), x0);
        }
    }
}

// ---------------- kernel 2: main ODE kernel ----------------
__global__ void __launch_bounds__(FF, 4)
ode_kernel(const float* __restrict__ X, float* __restrict__ O, int rows) {
    __shared__ float4 sCoef[NSEG * FF];   // 36 KB
    int f = threadIdx.x;
    // stage coefficient table (coalesced float4 loads)
    for (int i = threadIdx.x; i < NSEG * FF; i += FF) sCoef[i] = g_coef4[i];

    bool uni  = (g_uniform != 0);
    float2 ki = g_k0inv[f];
    float invh = ki.y;
    float nk0  = -ki.x * invh;
    float kn[NK];
    if (!uni) {
#pragma unroll
        for (int j = 0; j < NK; j++) kn[j] = g_knotsg[f * NK + j];
    }
    __syncthreads();
    const float4* tbl = sCoef + f;

    for (int row0 = blockIdx.x * VROWS; row0 < rows; row0 += gridDim.x * VROWS) {
        float st[VROWS];
#pragma unroll
        for (int v = 0; v < VROWS; v++) {
            int r = row0 + v;
            st[v] = (r < rows) ? X[(size_t)r * FF + f] : 0.0f;
        }
        if (uni) integrate<true >(st, nk0, invh, kn, f, tbl);
        else     integrate<false>(st, nk0, invh, kn, f, tbl);
#pragma unroll
        for (int v = 0; v < VROWS; v++) {
            int r = row0 + v;
            if (r < rows) O[(size_t)r * FF + f] = fminf(fmaxf(st[v], 0.0f), 1.0f);
        }
    }
}

// ---------------- harness entry ----------------
extern "C" void kernel_launch(void* const* d_in, const int* in_sizes, int n_in,
                              void* d_out, int out_size) {
    const float* x = (const float*)d_in[0];   // [B, 256] fp32
    const float* w = (const float*)d_in[1];   // [256, 10] fp32
    (void)n_in;
    int rows = in_sizes[0] / FF;

    coeff_kernel<<<1, FF>>>(w);

    int nblocks = 148 * 4;                    // 4 CTAs/SM target occupancy
    int maxb = (rows + VROWS - 1) / VROWS;
    if (nblocks > maxb) nblocks = maxb;
    ode_kernel<<<nblocks, FF>>>(x, (float*)d_out, rows);
    (void)out_size;
}

// round 3
// speedup vs baseline: 1.0609x; 1.0609x over previous
#include <cuda_runtime.h>

#define NK   10     // knots per feature
#define NSEG 9      // segments
#define FF   256    // features (fixed by problem)
#define VROWS 2     // rows per thread per iteration (ILP)
#define NCTA 6      // CTAs per SM

// ---------------- device-global scratch (no allocations allowed) ----------------
__device__ float4 g_coef4[NSEG * FF];   // [seg][f] : (y, b*h, c*h^2, d*h^3)  (normalized-w form)
__device__ float2 g_k0inv[FF];          // (k0, 1/h_avg) for uniform fast path
__device__ float  g_knotsg[FF * NK];    // [f][k] raw knots (generic-path scan)
__device__ float2 g_kx2[FF * NSEG];     // (kx_i, 1/h_i) generic-path per-segment
__device__ int    g_uniform;            // 1 if all features have (near-)uniform knots

// ---------------- kernel 1: per-feature natural cubic spline coefficients ----------------
__global__ void coeff_kernel(const float* __restrict__ W) {
    __shared__ int s_uni;
    int f = threadIdx.x;
    if (f == 0) s_uni = 1;
    __syncthreads();

    float kx[NK], yv[NK];
#pragma unroll
    for (int j = 0; j < NK; j++) {
        kx[j] = W[f * NK + j];
        yv[j] = (j & 1) ? -1.0f : 1.0f;
        g_knotsg[f * NK + j] = kx[j];
    }
    float h[NSEG], sl[NSEG];
#pragma unroll
    for (int j = 0; j < NSEG; j++) {
        h[j]  = kx[j + 1] - kx[j];
        sl[j] = (yv[j + 1] - yv[j]) / h[j];
    }
    // Thomas algorithm: m=8 interior second derivatives.
    float cp[8], dp[8];
    {
        float dg  = 2.0f * (h[0] + h[1]);
        float inv = 1.0f / dg;
        cp[0] = h[1] * inv;
        dp[0] = 6.0f * (sl[1] - sl[0]) * inv;
#pragma unroll
        for (int i = 1; i < 8; i++) {
            float dg2 = 2.0f * (h[i] + h[i + 1]);
            float sub = h[i];
            float den = dg2 - sub * cp[i - 1];
            float inv2 = 1.0f / den;
            cp[i] = (i < 7) ? h[i + 1] * inv2 : 0.0f;
            dp[i] = (6.0f * (sl[i + 1] - sl[i]) - sub * dp[i - 1]) * inv2;
        }
    }
    float M[NK];
    M[0] = 0.0f; M[9] = 0.0f;
    M[8] = dp[7];
#pragma unroll
    for (int i = 6; i >= 0; i--)
        M[i + 1] = dp[i] - cp[i] * M[i + 2];

    // uniformity check
    float havg  = (kx[9] - kx[0]) * (1.0f / 9.0f);
    float range = fabsf(kx[9] - kx[0]) + 1e-30f;
    float dev = 0.0f;
#pragma unroll
    for (int j = 0; j < NK; j++)
        dev = fmaxf(dev, fabsf(kx[j] - (kx[0] + (float)j * havg)));
    if (!(dev <= 1e-4f * range)) atomicAnd(&s_uni, 0);

#pragma unroll
    for (int i = 0; i < NSEG; i++) {
        float c = 0.5f * M[i];
        float d = (M[i + 1] - M[i]) / (6.0f * h[i]);
        float b = sl[i] - h[i] * (2.0f * M[i] + M[i + 1]) * (1.0f / 6.0f);
        float4 cf;
        cf.x = yv[i];                      // value at left knot
        cf.y = b * h[i];                   // linear coeff in w
        cf.z = c * h[i] * h[i];            // quadratic
        cf.w = d * h[i] * h[i] * h[i];     // cubic
        g_coef4[i * FF + f] = cf;
        g_kx2[f * NSEG + i] = make_float2(kx[i], 1.0f / h[i]);
    }
    g_k0inv[f] = make_float2(kx[0], 1.0f / havg);
    __syncthreads();
    if (f == 0) g_uniform = s_uni;
}

// ---------------- spline evaluation ----------------
__device__ __forceinline__ float spline_horner(float w, float4 cf) {
    return fmaf(w, fmaf(w, fmaf(w, cf.w, cf.z), cf.y), cf.x);
}

// Fast path: uniform knots. idx = clamp(floor(t), 0, 8); w = t - idx (UNclamped:
// edge segments extrapolate with negative / >1 w, matching the reference).
__device__ __forceinline__ float eval_uni(float x, float nk0, float invh,
                                          const float4* __restrict__ tbl) {
    float t  = fmaf(x, invh, nk0);
    float ft = floorf(t);
    ft = fminf(fmaxf(ft, 0.0f), 8.0f);
    float w = t - ft;
    int idx = (int)ft;
    float4 cf = tbl[idx * FF];     // conflict-free: [seg][f] layout, f = lane-consecutive
    return spline_horner(w, cf);
}

// Generic path (cold: only if knots are non-uniform). Register-light by design —
// scans knots straight from global so it doesn't inflate the hot path's regcount.
__device__ __forceinline__ float eval_gen(float x, int f,
                                          const float4* __restrict__ tbl) {
    int s = 0;
#pragma unroll
    for (int j = 1; j < NK; j++) s += (x >= __ldg(&g_knotsg[f * NK + j])) ? 1 : 0;
    int idx = min(s, NSEG - 1);
    float2 kv = __ldg(&g_kx2[f * NSEG + idx]);
    float w = (x - kv.x) * kv.y;
    float4 cf = tbl[idx * FF];
    return spline_horner(w, cf);
}

// ---------------- RK 3/8-rule integration (9 steps, dt = 1/9) ----------------
template<bool UNI>
__device__ __forceinline__ void integrate(float st[VROWS], float nk0, float invh,
                                          int f, const float4* __restrict__ tbl) {
    const float dt  = 1.0f / 9.0f;
    const float dt3 = dt * (1.0f / 3.0f);
    const float dt8 = dt * 0.125f;
#pragma unroll 1
    for (int s = 0; s < 9; s++) {
#pragma unroll
        for (int v = 0; v < VROWS; v++) {
            float x0 = st[v];
            float k1 = UNI ? eval_uni(x0, nk0, invh, tbl) : eval_gen(x0, f, tbl);
            float a2 = fmaf(dt3, k1, x0);
            float k2 = UNI ? eval_uni(a2, nk0, invh, tbl) : eval_gen(a2, f, tbl);
            float a3 = fmaf(dt, k2, fmaf(-dt3, k1, x0));
            float k3 = UNI ? eval_uni(a3, nk0, invh, tbl) : eval_gen(a3, f, tbl);
            float a4 = fmaf(dt, (k1 - k2) + k3, x0);
            float k4 = UNI ? eval_uni(a4, nk0, invh, tbl) : eval_gen(a4, f, tbl);
            st[v] = fmaf(dt8, fmaf(3.0f, k2 + k3, k1 + k4), x0);
        }
    }
}

// ---------------- kernel 2: main ODE kernel ----------------
__global__ void __launch_bounds__(FF, NCTA)
ode_kernel(const float* __restrict__ X, float* __restrict__ O, int rows) {
    __shared__ float4 sCoef[NSEG * FF];   // 36 KB; 6 CTA/SM -> 227 KB (fits exactly)
    int f = threadIdx.x;
    // stage coefficient table (coalesced float4 loads)
    for (int i = threadIdx.x; i < NSEG * FF; i += FF) sCoef[i] = g_coef4[i];

    bool uni  = (g_uniform != 0);
    float2 ki = g_k0inv[f];
    float invh = ki.y;
    float nk0  = -ki.x * invh;
    __syncthreads();
    const float4* tbl = sCoef + f;

    for (int row0 = blockIdx.x * VROWS; row0 < rows; row0 += gridDim.x * VROWS) {
        float st[VROWS];
#pragma unroll
        for (int v = 0; v < VROWS; v++) {
            int r = row0 + v;
            st[v] = (r < rows) ? X[(size_t)r * FF + f] : 0.0f;
        }
        if (uni) integrate<true >(st, nk0, invh, f, tbl);
        else     integrate<false>(st, nk0, invh, f, tbl);
#pragma unroll
        for (int v = 0; v < VROWS; v++) {
            int r = row0 + v;
            if (r < rows) O[(size_t)r * FF + f] = fminf(fmaxf(st[v], 0.0f), 1.0f);
        }
    }
}

// ---------------- harness entry ----------------
extern "C" void kernel_launch(void* const* d_in, const int* in_sizes, int n_in,
                              void* d_out, int out_size) {
    const float* x = (const float*)d_in[0];   // [B, 256] fp32
    const float* w = (const float*)d_in[1];   // [256, 10] fp32
    (void)n_in;
    int rows = in_sizes[0] / FF;

    coeff_kernel<<<1, FF>>>(w);

    int nblocks = 148 * NCTA;                 // 6 CTAs/SM
    int maxb = (rows + VROWS - 1) / VROWS;
    if (nblocks > maxb) nblocks = maxb;
    ode_kernel<<<nblocks, FF>>>(x, (float*)d_out, rows);
    (void)out_size;
}